// round 1
// baseline (speedup 1.0000x reference)
#include <cuda_runtime.h>
#include <cuda_bf16.h>
#include <math.h>

#define BB 16384
#define DD 512
#define HH (BB/2)     // 8192 pairs
#define KB 16384      // time buckets
#define NCOX 64       // cox/nll partial blocks

// ---------------- scratch (no allocations allowed) ----------------
__device__ float g_exp[BB];        // exp(hazard[i])
__device__ float g_bsum[KB];       // per-bucket sum of exp
__device__ int   g_bcnt[KB];       // per-bucket count
__device__ int   g_boff[KB];       // exclusive prefix of counts
__device__ int   g_bcur[KB];       // scatter cursors
__device__ float g_sfx[KB];        // suffix sum of g_bsum strictly above bucket b
__device__ int   g_perm[BB];       // counting-sorted indices (bucket-grouped)
__device__ float g_con[HH];        // per-pair softplus
__device__ float g_cox_num[NCOX];
__device__ float g_evs[NCOX];
__device__ float g_nll[NCOX];

// ---------------- init ----------------
__global__ void init_kernel() {
    int i = blockIdx.x * blockDim.x + threadIdx.x;
    if (i < KB) { g_bsum[i] = 0.f; g_bcnt[i] = 0; g_bcur[i] = 0; }
}

// ---------------- contrastive: one block per pair ----------------
__device__ __forceinline__ float dot4(float4 x, float4 y) {
    return fmaf(x.x, y.x, fmaf(x.y, y.y, fmaf(x.z, y.z, x.w * y.w)));
}

__global__ __launch_bounds__(128) void contrast_kernel(
    const float* __restrict__ r1, const float* __restrict__ r2,
    const float* __restrict__ r3,
    const int* __restrict__ x1, const int* __restrict__ x2)
{
    __shared__ float s_red[4][15];
    int m = blockIdx.x;
    int a = x1[m], b = x2[m];
    int t = threadIdx.x;           // 0..127, one float4 per row per thread

    const float4* A1 = (const float4*)(r1 + (size_t)a * DD);
    const float4* A2 = (const float4*)(r2 + (size_t)a * DD);
    const float4* A3 = (const float4*)(r3 + (size_t)a * DD);
    const float4* B1 = (const float4*)(r1 + (size_t)b * DD);
    const float4* B2 = (const float4*)(r2 + (size_t)b * DD);
    const float4* B3 = (const float4*)(r3 + (size_t)b * DD);

    float4 a1 = A1[t], a2 = A2[t], a3 = A3[t];
    float4 b1 = B1[t], b2 = B2[t], b3 = B3[t];

    float acc[15];
    acc[0]  = dot4(a1, a1);  acc[1]  = dot4(a2, a2);  acc[2]  = dot4(a3, a3);
    acc[3]  = dot4(b1, b1);  acc[4]  = dot4(b2, b2);  acc[5]  = dot4(b3, b3);
    acc[6]  = dot4(a1, a2);  acc[7]  = dot4(a1, a3);  acc[8]  = dot4(a2, a3);
    acc[9]  = dot4(b1, b2);  acc[10] = dot4(b1, b3);  acc[11] = dot4(b2, b3);
    acc[12] = dot4(a1, b1);  acc[13] = dot4(a2, b2);  acc[14] = dot4(a3, b3);

    int lane = t & 31, warp = t >> 5;
#pragma unroll
    for (int q = 0; q < 15; q++) {
        float v = acc[q];
#pragma unroll
        for (int o = 16; o > 0; o >>= 1) v += __shfl_xor_sync(0xffffffffu, v, o);
        if (lane == 0) s_red[warp][q] = v;
    }
    __syncthreads();

    if (t == 0) {
        float s[15];
#pragma unroll
        for (int q = 0; q < 15; q++)
            s[q] = s_red[0][q] + s_red[1][q] + s_red[2][q] + s_red[3][q];

        const float EPS = 1e-8f;
        float n1a = fmaxf(sqrtf(s[0]), EPS), n2a = fmaxf(sqrtf(s[1]), EPS), n3a = fmaxf(sqrtf(s[2]), EPS);
        float n1b = fmaxf(sqrtf(s[3]), EPS), n2b = fmaxf(sqrtf(s[4]), EPS), n3b = fmaxf(sqrtf(s[5]), EPS);

        float dis_xx = s[6] / (n1a * n2a) + s[7] / (n1a * n3a) + s[8] / (n2a * n3a);
        float dis_yy = s[9] / (n1b * n2b) + s[10] / (n1b * n3b) + s[11] / (n2b * n3b);
        float dis_xy = s[12] / (n1a * n1b) + s[13] / (n2a * n2b) + s[14] / (n3a * n3b);

        float z = 0.2f + dis_xy - 0.5f * dis_xx - 0.5f * dis_yy;
        float sp = (z > 0.f) ? (z + log1pf(expf(-z))) : log1pf(expf(z));
        g_con[m] = sp;
    }
}

// ---------------- cox step 1: bucket counts + sums ----------------
__device__ __forceinline__ int bucket_of(float t) {
    int b = (int)(t * (float)KB);
    if (b < 0) b = 0;
    if (b > KB - 1) b = KB - 1;
    return b;
}

__global__ void count_kernel(const float* __restrict__ hazard,
                             const float* __restrict__ time)
{
    int i = blockIdx.x * blockDim.x + threadIdx.x;
    if (i >= BB) return;
    float e = expf(hazard[i]);
    g_exp[i] = e;
    int bkt = bucket_of(time[i]);
    atomicAdd(&g_bsum[bkt], e);
    atomicAdd(&g_bcnt[bkt], 1);
}

// ---------------- cox step 2: scans (1 block, 1024 threads, 16 buckets/thread) ----------------
__global__ __launch_bounds__(1024) void scan_kernel() {
    __shared__ int   swi[32];
    __shared__ float swf[32];
    int t = threadIdx.x;
    int base = t * 16;
    int lane = t & 31, warp = t >> 5;

    int   cl[16]; float fl[16];
    int csum = 0; float fsum = 0.f;
#pragma unroll
    for (int j = 0; j < 16; j++) {
        cl[j] = g_bcnt[base + j]; csum += cl[j];
        fl[j] = g_bsum[base + j]; fsum += fl[j];
    }

    // ---- int inclusive scan across 1024 threads ----
    int vi = csum;
#pragma unroll
    for (int o = 1; o < 32; o <<= 1) {
        int u = __shfl_up_sync(0xffffffffu, vi, o);
        if (lane >= o) vi += u;
    }
    if (lane == 31) swi[warp] = vi;

    // ---- float inclusive scan ----
    float vf = fsum;
#pragma unroll
    for (int o = 1; o < 32; o <<= 1) {
        float u = __shfl_up_sync(0xffffffffu, vf, o);
        if (lane >= o) vf += u;
    }
    if (lane == 31) swf[warp] = vf;
    __syncthreads();

    if (warp == 0) {
        int   wi = swi[lane];
        float wf = swf[lane];
#pragma unroll
        for (int o = 1; o < 32; o <<= 1) {
            int   ui = __shfl_up_sync(0xffffffffu, wi, o);
            float uf = __shfl_up_sync(0xffffffffu, wf, o);
            if (lane >= o) { wi += ui; wf += uf; }
        }
        swi[lane] = wi;  // inclusive warp-total prefix
        swf[lane] = wf;
    }
    __syncthreads();

    int   incl_i = vi + (warp ? swi[warp - 1] : 0);
    float incl_f = vf + (warp ? swf[warp - 1] : 0.f);
    float total_f = swf[31];

    // offsets = exclusive prefix of counts
    int run = incl_i - csum;
#pragma unroll
    for (int j = 0; j < 16; j++) { g_boff[base + j] = run; run += cl[j]; }

    // suffix sums strictly above each bucket
    float run2 = total_f - incl_f;   // sum of all buckets to the right of this chunk
#pragma unroll
    for (int j = 15; j >= 0; j--) { g_sfx[base + j] = run2; run2 += fl[j]; }
}

// ---------------- cox step 3: scatter into bucket-grouped order ----------------
__global__ void scatter_kernel(const float* __restrict__ time) {
    int i = blockIdx.x * blockDim.x + threadIdx.x;
    if (i >= BB) return;
    int bkt = bucket_of(time[i]);
    int slot = g_boff[bkt] + atomicAdd(&g_bcur[bkt], 1);
    g_perm[slot] = i;
}

// ---------------- cox step 4: per-element evaluation + nll partials ----------------
__global__ __launch_bounds__(256) void coxeval_kernel(
    const float* __restrict__ hazard, const float* __restrict__ time,
    const int* __restrict__ event, const float* __restrict__ score)
{
    __shared__ float s_n[8], s_e[8], s_l[8];
    int i = blockIdx.x * blockDim.x + threadIdx.x;

    float num = 0.f, evs = 0.f, nll = 0.f;
    if (i < BB) {
        float ti = time[i];
        int bkt = bucket_of(ti);
        float S = g_sfx[bkt] + g_exp[i];
        int start = g_boff[bkt], cnt = g_bcnt[bkt];
        for (int s = start; s < start + cnt; s++) {
            int j = g_perm[s];
            if (j == i) continue;
            float tj = time[j];
            if (tj > ti || (tj == ti && j < i)) S += g_exp[j];
        }
        float lr = logf(S + 1e-6f);
        int ev = event[i];
        float evf = (float)ev;
        num = evf * (hazard[i] - lr);
        evs = evf;
        nll = score[i * 2 + ev];
    }

    int lane = threadIdx.x & 31, warp = threadIdx.x >> 5;
#pragma unroll
    for (int o = 16; o > 0; o >>= 1) {
        num += __shfl_xor_sync(0xffffffffu, num, o);
        evs += __shfl_xor_sync(0xffffffffu, evs, o);
        nll += __shfl_xor_sync(0xffffffffu, nll, o);
    }
    if (lane == 0) { s_n[warp] = num; s_e[warp] = evs; s_l[warp] = nll; }
    __syncthreads();
    if (threadIdx.x == 0) {
        float a = 0.f, b = 0.f, c = 0.f;
        for (int w = 0; w < 8; w++) { a += s_n[w]; b += s_e[w]; c += s_l[w]; }
        g_cox_num[blockIdx.x] = a;
        g_evs[blockIdx.x]     = b;
        g_nll[blockIdx.x]     = c;
    }
}

// ---------------- final deterministic reduce ----------------
__global__ __launch_bounds__(256) void final_kernel(float* __restrict__ out) {
    __shared__ float sc[8], sn[8], sx[8], se[8];
    int t = threadIdx.x;

    float cs = 0.f;
    for (int i = t; i < HH; i += 256) cs += g_con[i];

    float nl = 0.f, cx = 0.f, ev = 0.f;
    if (t < NCOX) { nl = g_nll[t]; cx = g_cox_num[t]; ev = g_evs[t]; }

    int lane = t & 31, warp = t >> 5;
#pragma unroll
    for (int o = 16; o > 0; o >>= 1) {
        cs += __shfl_xor_sync(0xffffffffu, cs, o);
        nl += __shfl_xor_sync(0xffffffffu, nl, o);
        cx += __shfl_xor_sync(0xffffffffu, cx, o);
        ev += __shfl_xor_sync(0xffffffffu, ev, o);
    }
    if (lane == 0) { sc[warp] = cs; sn[warp] = nl; sx[warp] = cx; se[warp] = ev; }
    __syncthreads();
    if (t == 0) {
        float CS = 0.f, NL = 0.f, CX = 0.f, EV = 0.f;
        for (int w = 0; w < 8; w++) { CS += sc[w]; NL += sn[w]; CX += sx[w]; EV += se[w]; }
        float nll = -NL / (float)BB;
        float cox = -CX / (EV + 1e-6f);
        float con = CS / (float)HH;
        out[0] = nll + cox + 0.3f * con;
    }
}

// ---------------- launch ----------------
extern "C" void kernel_launch(void* const* d_in, const int* in_sizes, int n_in,
                              void* d_out, int out_size) {
    const float* rep1   = (const float*)d_in[0];
    const float* rep2   = (const float*)d_in[1];
    const float* rep3   = (const float*)d_in[2];
    const float* hazard = (const float*)d_in[3];
    const float* score  = (const float*)d_in[4];
    const float* time_  = (const float*)d_in[5];
    const int*   event  = (const int*)d_in[6];
    const int*   x1_idx = (const int*)d_in[7];
    const int*   x2_idx = (const int*)d_in[8];
    float* out = (float*)d_out;

    init_kernel<<<KB / 256, 256>>>();
    count_kernel<<<BB / 256, 256>>>(hazard, time_);
    scan_kernel<<<1, 1024>>>();
    scatter_kernel<<<BB / 256, 256>>>(time_);
    coxeval_kernel<<<NCOX, 256>>>(hazard, time_, event, score);
    contrast_kernel<<<HH, 128>>>(rep1, rep2, rep3, x1_idx, x2_idx);
    final_kernel<<<1, 256>>>(out);
}

// round 2
// speedup vs baseline: 1.3770x; 1.3770x over previous
#include <cuda_runtime.h>
#include <cuda_bf16.h>
#include <math.h>

#define BB 16384
#define DD 512
#define HH 8192
#define KBK 16384

// ---------------- scratch ----------------
__device__ float g_exp[BB];
__device__ float g_bsum[KBK];
__device__ int   g_bcnt[KBK];
__device__ int   g_boff[KBK];
__device__ float g_sfx[KBK];
__device__ int   g_perm[BB];
__device__ float g_con[HH];
__device__ float g_part[192];        // [0:64) num, [64:128) evs, [128:192) nll
__device__ int   g_cnt_done  = 0;
__device__ int   g_scat_done = 0;
__device__ int   g_eval_done = 0;

__device__ __forceinline__ int bucket_of(float t) {
    int b = (int)(t * 16384.0f);
    if (b < 0) b = 0;
    if (b > KBK - 1) b = KBK - 1;
    return b;
}

__device__ __forceinline__ float dot4(float4 x, float4 y) {
    return fmaf(x.x, y.x, fmaf(x.y, y.y, fmaf(x.z, y.z, x.w * y.w)));
}

// =====================================================================
// K1: block 0 = cox master (spin -> scan). blocks 1..64 = histogram
//     feeders (then contrast). blocks 1..2048 = 4 contrast pairs each.
// =====================================================================
__global__ __launch_bounds__(512) void k1_kernel(
    const float* __restrict__ r1, const float* __restrict__ r2,
    const float* __restrict__ r3,
    const float* __restrict__ hazard, const float* __restrict__ time_,
    const int* __restrict__ x1, const int* __restrict__ x2)
{
    int blk = blockIdx.x, tid = threadIdx.x;
    int lane = tid & 31, warp = tid >> 5;

    __shared__ float s_red[16][15];
    __shared__ int   s_ci[16];
    __shared__ float s_cf[16];

    if (blk == 0) {
        // ---- master: wait for all 64 histogram feeders ----
        if (tid == 0) {
            volatile int* p = &g_cnt_done;
            while (*p < 64) __nanosleep(64);
            g_cnt_done = 0;
        }
        __syncthreads();
        __threadfence();

        // ---- scan: warp w owns buckets [w*1024, w*1024+1024) ----
        int base = warp * 1024;
        int csum = 0; float fsum = 0.f;
        for (int r = 0; r < 32; r++) {
            int idx = base + r * 32 + lane;
            csum += g_bcnt[idx];
            fsum += g_bsum[idx];
        }
#pragma unroll
        for (int o = 16; o > 0; o >>= 1) {
            csum += __shfl_xor_sync(0xffffffffu, csum, o);
            fsum += __shfl_xor_sync(0xffffffffu, fsum, o);
        }
        if (lane == 0) { s_ci[warp] = csum; s_cf[warp] = fsum; }
        __syncthreads();

        int ibase = 0; float fsuf = 0.f;
        for (int w = 0; w < 16; w++) {
            if (w < warp) ibase += s_ci[w];
            if (w > warp) fsuf  += s_cf[w];
        }

        // int exclusive prefix (counts -> boff)
        int icarry = ibase;
        for (int r = 0; r < 32; r++) {
            int idx = base + r * 32 + lane;
            int c = g_bcnt[idx];
            int inc = c;
#pragma unroll
            for (int o = 1; o < 32; o <<= 1) {
                int u = __shfl_up_sync(0xffffffffu, inc, o);
                if (lane >= o) inc += u;
            }
            g_boff[idx] = icarry + inc - c;
            icarry += __shfl_sync(0xffffffffu, inc, 31);
        }

        // float strict-suffix (bsum -> sfx)
        float fcarry = fsuf;
        for (int r = 31; r >= 0; r--) {
            int idx = base + r * 32 + lane;
            float v = g_bsum[idx];
            float incR = v;
#pragma unroll
            for (int o = 1; o < 32; o <<= 1) {
                float u = __shfl_down_sync(0xffffffffu, incR, o);
                if (lane < 32 - o) incR += u;
            }
            g_sfx[idx] = fcarry + incR - v;
            fcarry += __shfl_sync(0xffffffffu, incR, 0);
        }
        __syncthreads();
        // reset bsum for next run
        for (int i = tid; i < KBK; i += 512) g_bsum[i] = 0.f;
        return;
    }

    // ---- histogram feeders: blocks 1..64, 256 elements each ----
    if (blk <= 64) {
        if (tid < 256) {
            int i = (blk - 1) * 256 + tid;
            float e = expf(hazard[i]);
            g_exp[i] = e;
            int b = bucket_of(time_[i]);
            atomicAdd(&g_bsum[b], e);
            atomicAdd(&g_bcnt[b], 1);
        }
        __threadfence();
        __syncthreads();
        if (tid == 0) atomicAdd(&g_cnt_done, 1);
    }

    // ---- contrast: 4 pairs per block, 128 threads per pair ----
    int group = tid >> 7, gt = tid & 127;
    int m = (blk - 1) * 4 + group;
    int a = x1[m], b = x2[m];

    const float4* A1 = (const float4*)(r1 + (size_t)a * DD);
    const float4* A2 = (const float4*)(r2 + (size_t)a * DD);
    const float4* A3 = (const float4*)(r3 + (size_t)a * DD);
    const float4* B1 = (const float4*)(r1 + (size_t)b * DD);
    const float4* B2 = (const float4*)(r2 + (size_t)b * DD);
    const float4* B3 = (const float4*)(r3 + (size_t)b * DD);

    float4 a1 = A1[gt], a2 = A2[gt], a3 = A3[gt];
    float4 b1 = B1[gt], b2 = B2[gt], b3 = B3[gt];

    float acc[15];
    acc[0]  = dot4(a1, a1);  acc[1]  = dot4(a2, a2);  acc[2]  = dot4(a3, a3);
    acc[3]  = dot4(b1, b1);  acc[4]  = dot4(b2, b2);  acc[5]  = dot4(b3, b3);
    acc[6]  = dot4(a1, a2);  acc[7]  = dot4(a1, a3);  acc[8]  = dot4(a2, a3);
    acc[9]  = dot4(b1, b2);  acc[10] = dot4(b1, b3);  acc[11] = dot4(b2, b3);
    acc[12] = dot4(a1, b1);  acc[13] = dot4(a2, b2);  acc[14] = dot4(a3, b3);

#pragma unroll
    for (int q = 0; q < 15; q++) {
        float v = acc[q];
#pragma unroll
        for (int o = 16; o > 0; o >>= 1) v += __shfl_xor_sync(0xffffffffu, v, o);
        if (lane == 0) s_red[warp][q] = v;
    }
    __syncthreads();

    if (gt == 0) {
        int w0 = group * 4;
        float s[15];
#pragma unroll
        for (int q = 0; q < 15; q++)
            s[q] = s_red[w0][q] + s_red[w0+1][q] + s_red[w0+2][q] + s_red[w0+3][q];

        const float EPS = 1e-8f;
        float n1a = fmaxf(sqrtf(s[0]), EPS), n2a = fmaxf(sqrtf(s[1]), EPS), n3a = fmaxf(sqrtf(s[2]), EPS);
        float n1b = fmaxf(sqrtf(s[3]), EPS), n2b = fmaxf(sqrtf(s[4]), EPS), n3b = fmaxf(sqrtf(s[5]), EPS);

        float dis_xx = s[6] / (n1a * n2a) + s[7]  / (n1a * n3a) + s[8]  / (n2a * n3a);
        float dis_yy = s[9] / (n1b * n2b) + s[10] / (n1b * n3b) + s[11] / (n2b * n3b);
        float dis_xy = s[12] / (n1a * n1b) + s[13] / (n2a * n2b) + s[14] / (n3a * n3b);

        float z = 0.2f + dis_xy - 0.5f * dis_xx - 0.5f * dis_yy;
        float sp = (z > 0.f) ? (z + log1pf(expf(-z))) : log1pf(expf(z));
        g_con[m] = sp;
    }
}

// =====================================================================
// K2: 64 blocks x 256. scatter -> grid spin barrier -> eval -> last
//     finisher does deterministic final reduce + scratch resets.
// =====================================================================
__global__ __launch_bounds__(256) void k2_kernel(
    const float* __restrict__ hazard, const float* __restrict__ time_,
    const int* __restrict__ event, const float* __restrict__ score,
    float* __restrict__ out)
{
    int blk = blockIdx.x, tid = threadIdx.x;
    int lane = tid & 31, warp = tid >> 5;
    int i = blk * 256 + tid;

    __shared__ int   s_go;
    __shared__ float s_n[8], s_e[8], s_l[8], s_c[8];

    // ---- phase A: scatter ----
    float ti = time_[i];
    int bkt = bucket_of(ti);
    int slot = atomicAdd(&g_boff[bkt], 1);
    g_perm[slot] = i;
    __threadfence();
    __syncthreads();
    if (tid == 0) {
        atomicAdd(&g_scat_done, 1);
        volatile int* p = &g_scat_done;
        while (*p < 64) __nanosleep(32);
    }
    __syncthreads();
    __threadfence();

    // ---- phase B: eval ----
    float e_i = g_exp[i];
    float S = g_sfx[bkt] + e_i;
    int cnt = g_bcnt[bkt];
    int start = g_boff[bkt] - cnt;
    for (int s = start; s < start + cnt; s++) {
        int j = g_perm[s];
        if (j == i) continue;
        float tj = time_[j];
        if (tj > ti || (tj == ti && j < i)) S += g_exp[j];
    }
    float lr = logf(S + 1e-6f);
    int ev = event[i];
    float evf = (float)ev;
    float num = evf * (hazard[i] - lr);
    float evs = evf;
    float nll = score[2 * i + ev];

#pragma unroll
    for (int o = 16; o > 0; o >>= 1) {
        num += __shfl_xor_sync(0xffffffffu, num, o);
        evs += __shfl_xor_sync(0xffffffffu, evs, o);
        nll += __shfl_xor_sync(0xffffffffu, nll, o);
    }
    if (lane == 0) { s_n[warp] = num; s_e[warp] = evs; s_l[warp] = nll; }
    __syncthreads();
    if (tid == 0) {
        float a = 0.f, b = 0.f, c = 0.f;
        for (int w = 0; w < 8; w++) { a += s_n[w]; b += s_e[w]; c += s_l[w]; }
        g_part[blk]       = a;
        g_part[64 + blk]  = b;
        g_part[128 + blk] = c;
        __threadfence();
        int old = atomicAdd(&g_eval_done, 1);
        s_go = (old == 63) ? 1 : 0;
    }
    __syncthreads();

    // ---- finisher: final deterministic reduce + resets ----
    if (s_go) {
        __threadfence();
        for (int b2 = tid; b2 < KBK; b2 += 256) g_bcnt[b2] = 0;

        float cs = 0.f;
        for (int q = tid; q < HH; q += 256) cs += g_con[q];
        float pn = 0.f, pe = 0.f, pl = 0.f;
        if (tid < 64) {
            pn = g_part[tid];
            pe = g_part[64 + tid];
            pl = g_part[128 + tid];
        }
#pragma unroll
        for (int o = 16; o > 0; o >>= 1) {
            cs += __shfl_xor_sync(0xffffffffu, cs, o);
            pn += __shfl_xor_sync(0xffffffffu, pn, o);
            pe += __shfl_xor_sync(0xffffffffu, pe, o);
            pl += __shfl_xor_sync(0xffffffffu, pl, o);
        }
        if (lane == 0) { s_c[warp] = cs; s_n[warp] = pn; s_e[warp] = pe; s_l[warp] = pl; }
        __syncthreads();
        if (tid == 0) {
            float CS = 0.f, PN = 0.f, PE = 0.f, PL = 0.f;
            for (int w = 0; w < 8; w++) {
                CS += s_c[w]; PN += s_n[w]; PE += s_e[w]; PL += s_l[w];
            }
            float nll_ = -PL / (float)BB;
            float cox  = -PN / (PE + 1e-6f);
            float con  = CS / (float)HH;
            out[0] = nll_ + cox + 0.3f * con;
            g_scat_done = 0;
            g_eval_done = 0;
        }
    }
}

// ---------------- launch ----------------
extern "C" void kernel_launch(void* const* d_in, const int* in_sizes, int n_in,
                              void* d_out, int out_size) {
    const float* rep1   = (const float*)d_in[0];
    const float* rep2   = (const float*)d_in[1];
    const float* rep3   = (const float*)d_in[2];
    const float* hazard = (const float*)d_in[3];
    const float* score  = (const float*)d_in[4];
    const float* time_  = (const float*)d_in[5];
    const int*   event  = (const int*)d_in[6];
    const int*   x1_idx = (const int*)d_in[7];
    const int*   x2_idx = (const int*)d_in[8];
    float* out = (float*)d_out;

    k1_kernel<<<2049, 512>>>(rep1, rep2, rep3, hazard, time_, x1_idx, x2_idx);
    k2_kernel<<<64, 256>>>(hazard, time_, event, score, out);
}